// round 1
// baseline (speedup 1.0000x reference)
#include <cuda_runtime.h>

// Rows of 8 fp32 experts. Expert 0 is selected into the top-2 iff fewer than
// 2 of experts 1..7 strictly exceed x[row][0] (top_k tie-break favors lower
// index, so ties never evict expert 0). If selected, copy the row; else zero.
__global__ void __launch_bounds__(256) routing_kernel(
    const float4* __restrict__ in, float4* __restrict__ out, int nrows)
{
    int i = blockIdx.x * blockDim.x + threadIdx.x;
    if (i >= nrows) return;

    float4 a = in[2 * i];       // experts 0..3
    float4 b = in[2 * i + 1];   // experts 4..7

    float v0 = a.x;
    int gt = (a.y > v0) + (a.z > v0) + (a.w > v0)
           + (b.x > v0) + (b.y > v0) + (b.z > v0) + (b.w > v0);

    if (gt >= 2) {
        a = make_float4(0.f, 0.f, 0.f, 0.f);
        b = make_float4(0.f, 0.f, 0.f, 0.f);
    }

    out[2 * i]     = a;
    out[2 * i + 1] = b;
}

extern "C" void kernel_launch(void* const* d_in, const int* in_sizes, int n_in,
                              void* d_out, int out_size)
{
    const float4* in = (const float4*)d_in[0];
    float4* out = (float4*)d_out;
    int nrows = in_sizes[0] / 8;   // 8 experts per row

    int threads = 256;
    int blocks = (nrows + threads - 1) / threads;
    routing_kernel<<<blocks, threads>>>(in, out, nrows);
}